// round 14
// baseline (speedup 1.0000x reference)
#include <cuda_runtime.h>
#include <math.h>

#define FFT_N    8192
#define HALF_N   4096
#define THREADS  512
// alignment-preserving pad: +2 float2 (16B) per 32 float2.
#define PAD(i)   ((i) + (((i) >> 5) << 1))
#define PADN     (FFT_N + (FFT_N >> 4))      // 8704 float2
#define UPO      4352                         // PAD(4096)

// twiddle table layout (entries)
#define TBL_A    0      // FFT1 p1: 32 rows x 16 (q=1..15 used)
#define TBL_B    512    // FFT1 p2: 1 row x 16
#define TBL_C    528    // FFT2 m=8:  64 rows x 8 (q=1..7 used)
#define TBL_D    1040   // FFT2 m=64:  8 rows x 8
#define TBL_TOT  1104

// ---------------- compile-time twiddle table ----------------
struct CF { float x, y; };
struct alignas(16) TwTab { CF w[TBL_TOT]; };

constexpr double PI_D  = 3.14159265358979323846264338328;
constexpr double TH1_D = -2.0 * PI_D / 8192.0;
constexpr double TH2_D = -2.0 * PI_D / 4096.0;

constexpr double poly_sin_ct(double r) {
    const double r2 = r * r;
    return r * (1.0 + r2 * (-1.0/6.0 + r2 * (1.0/120.0 + r2 * (-1.0/5040.0
             + r2 * (1.0/362880.0 + r2 * (-1.0/39916800.0))))));
}
constexpr double poly_cos_ct(double r) {
    const double r2 = r * r;
    return 1.0 + r2 * (-0.5 + r2 * (1.0/24.0 + r2 * (-1.0/720.0
             + r2 * (1.0/40320.0 + r2 * (-1.0/3628800.0)))));
}
struct SC { double s, c; };
constexpr SC sincos_ct(double x) {
    const double h = PI_D * 0.5;
    const double t = x / h;
    const long long k = (long long)(t >= 0 ? t + 0.5 : t - 0.5);
    const double r = x - (double)k * h;
    const int q = (int)(((k % 4) + 4) % 4);
    const double ps = poly_sin_ct(r), pc = poly_cos_ct(r);
    SC o{0.0, 0.0};
    if      (q == 0) { o.s =  ps; o.c =  pc; }
    else if (q == 1) { o.s =  pc; o.c = -ps; }
    else if (q == 2) { o.s = -ps; o.c = -pc; }
    else             { o.s = -pc; o.c =  ps; }
    return o;
}
constexpr TwTab make_tw() {
    TwTab t{};
    for (int e = 0; e < TBL_TOT; e++) {
        double ang = 0.0;
        if (e < TBL_B) {
            const int j = e >> 4, q = (e & 15) + 1;
            ang = TH1_D * (double)(16 * j * q);
        } else if (e < TBL_C) {
            const int q = e - TBL_B + 1;
            ang = TH1_D * (double)(256 * q);
        } else if (e < TBL_D) {
            const int r2 = e - TBL_C;
            const int j = r2 >> 3, q = (r2 & 7) + 1;
            ang = TH2_D * (double)(8 * j * q);
        } else {
            const int r2 = e - TBL_D;
            const int j = r2 >> 3, q = (r2 & 7) + 1;
            ang = TH2_D * (double)(64 * j * q);
        }
        const SC sc = sincos_ct(ang);
        t.w[e].x = (float)sc.c;
        t.w[e].y = (float)sc.s;
    }
    return t;
}
__constant__ TwTab TWC = make_tw();

__device__ constexpr int SLOT[16] = {0,4,8,12, 1,5,9,13, 2,6,10,14, 3,7,11,15};

__device__ __forceinline__ float2 cadd(float2 a, float2 b){ return make_float2(a.x+b.x, a.y+b.y); }
__device__ __forceinline__ float2 csub(float2 a, float2 b){ return make_float2(a.x-b.x, a.y-b.y); }
__device__ __forceinline__ float2 cmul(float2 a, float2 b){
    return make_float2(a.x*b.x - a.y*b.y, a.x*b.y + a.y*b.x);
}
__device__ __forceinline__ float2 cmul_negi(float2 a){ return make_float2(a.y, -a.x); }

// In-place 16-point DFT (e^-). Output y[q] at a[SLOT[q]].
__device__ __forceinline__ void bfly16(float2 a[16]) {
    const float C  = 0.70710678118654752f;
    const float c8 = 0.92387953251128676f;
    const float s8 = 0.38268343236508977f;
    #pragma unroll
    for (int n0 = 0; n0 < 4; n0++) {
        float2 p0 = a[n0], p1 = a[n0+4], p2 = a[n0+8], p3 = a[n0+12];
        float2 t0 = cadd(p0,p2), t1 = csub(p0,p2);
        float2 t2 = cadd(p1,p3);
        float2 t3 = cmul_negi(csub(p1,p3));
        a[n0]    = cadd(t0,t2);
        a[n0+4]  = cadd(t1,t3);
        a[n0+8]  = csub(t0,t2);
        a[n0+12] = csub(t1,t3);
    }
    { float2 v=a[5];  a[5]  = make_float2( c8*v.x + s8*v.y,  c8*v.y - s8*v.x); }
    { float2 v=a[6];  a[6]  = make_float2( C*(v.x+v.y),      C*(v.y-v.x)); }
    { float2 v=a[7];  a[7]  = make_float2( s8*v.x + c8*v.y,  s8*v.y - c8*v.x); }
    { float2 v=a[9];  a[9]  = make_float2( C*(v.x+v.y),      C*(v.y-v.x)); }
    { float2 v=a[10]; a[10] = make_float2( v.y, -v.x); }
    { float2 v=a[11]; a[11] = make_float2( C*(v.y-v.x),     -C*(v.x+v.y)); }
    { float2 v=a[13]; a[13] = make_float2( s8*v.x + c8*v.y,  s8*v.y - c8*v.x); }
    { float2 v=a[14]; a[14] = make_float2( C*(v.y-v.x),     -C*(v.x+v.y)); }
    { float2 v=a[15]; a[15] = make_float2(-c8*v.x - s8*v.y,  s8*v.x - c8*v.y); }
    #pragma unroll
    for (int k0 = 0; k0 < 4; k0++) {
        float2 p0 = a[4*k0], p1 = a[4*k0+1], p2 = a[4*k0+2], p3 = a[4*k0+3];
        float2 t0 = cadd(p0,p2), t1 = csub(p0,p2);
        float2 t2 = cadd(p1,p3);
        float2 t3 = cmul_negi(csub(p1,p3));
        a[4*k0]   = cadd(t0,t2);
        a[4*k0+1] = cadd(t1,t3);
        a[4*k0+2] = csub(t0,t2);
        a[4*k0+3] = csub(t1,t3);
    }
}

// 8-point DFT, natural-order outputs in place.
__device__ __forceinline__ void bfly8(float2 a[8]) {
    const float C = 0.70710678118654752f;
    float2 u0 = cadd(a[0], a[4]), u1 = csub(a[0], a[4]);
    float2 u2 = cadd(a[2], a[6]), u3 = csub(a[2], a[6]);
    float2 E0 = cadd(u0, u2), E2 = csub(u0, u2);
    float2 mi3 = cmul_negi(u3);
    float2 E1 = cadd(u1, mi3), E3 = csub(u1, mi3);
    float2 v0 = cadd(a[1], a[5]), v1 = csub(a[1], a[5]);
    float2 v2 = cadd(a[3], a[7]), v3 = csub(a[3], a[7]);
    float2 O0 = cadd(v0, v2), O2 = csub(v0, v2);
    float2 ni3 = cmul_negi(v3);
    float2 O1 = cadd(v1, ni3), O3 = csub(v1, ni3);
    float2 w1O = make_float2(C*(O1.x+O1.y), C*(O1.y-O1.x));
    float2 w2O = cmul_negi(O2);
    float2 w3O = make_float2(C*(O3.y-O3.x), -C*(O3.x+O3.y));
    a[0]=cadd(E0,O0);  a[4]=csub(E0,O0);
    a[1]=cadd(E1,w1O); a[5]=csub(E1,w1O);
    a[2]=cadd(E2,w2O); a[6]=csub(E2,w2O);
    a[3]=cadd(E3,w3O); a[7]=csub(E3,w3O);
}

// Tree-structured twiddle generation + apply (FFT1 pass 0 only).
__device__ __forceinline__ void stage_twiddle0(float2 a[16], int jm, float theta_step) {
    float sn, cs;
    __sincosf(theta_step * (float)jm, &sn, &cs);
    const float2 w1 = make_float2(cs, sn);
    const float2 w2 = cmul(w1, w1);
    const float2 w3 = cmul(w2, w1);
    const float2 w4 = cmul(w2, w2);
    const float2 w5 = cmul(w4, w1);
    const float2 w6 = cmul(w4, w2);
    const float2 w7 = cmul(w4, w3);
    const float2 w8 = cmul(w4, w4);
    a[SLOT[1]]  = cmul(a[SLOT[1]],  w1);
    a[SLOT[2]]  = cmul(a[SLOT[2]],  w2);
    a[SLOT[3]]  = cmul(a[SLOT[3]],  w3);
    a[SLOT[4]]  = cmul(a[SLOT[4]],  w4);
    a[SLOT[5]]  = cmul(a[SLOT[5]],  w5);
    a[SLOT[6]]  = cmul(a[SLOT[6]],  w6);
    a[SLOT[7]]  = cmul(a[SLOT[7]],  w7);
    a[SLOT[8]]  = cmul(a[SLOT[8]],  w8);
    a[SLOT[9]]  = cmul(a[SLOT[9]],  cmul(w8, w1));
    a[SLOT[10]] = cmul(a[SLOT[10]], cmul(w8, w2));
    a[SLOT[11]] = cmul(a[SLOT[11]], cmul(w8, w3));
    a[SLOT[12]] = cmul(a[SLOT[12]], cmul(w8, w4));
    a[SLOT[13]] = cmul(a[SLOT[13]], cmul(w8, w5));
    a[SLOT[14]] = cmul(a[SLOT[14]], cmul(w8, w6));
    a[SLOT[15]] = cmul(a[SLOT[15]], cmul(w8, w7));
}

// 15-twiddle apply from a 16-entry constant table row (LDC.128 x8)
__device__ __forceinline__ void apply_tw15(float2 a[16], int rowbase) {
    const float4* w4 = reinterpret_cast<const float4*>(&TWC.w[rowbase]);
    float2 w[16];
    #pragma unroll
    for (int h = 0; h < 8; h++) {
        const float4 v = w4[h];
        w[2*h]   = make_float2(v.x, v.y);
        w[2*h+1] = make_float2(v.z, v.w);
    }
    #pragma unroll
    for (int q = 1; q < 16; q++) a[SLOT[q]] = cmul(a[SLOT[q]], w[q-1]);
}

// 7-twiddle apply from an 8-entry constant table row (LDC.128 x4)
__device__ __forceinline__ void apply_tw7(float2 a[8], int rowbase) {
    const float4* w4 = reinterpret_cast<const float4*>(&TWC.w[rowbase]);
    const float4 v0 = w4[0], v1 = w4[1], v2 = w4[2], v3 = w4[3];
    a[1] = cmul(a[1], make_float2(v0.x, v0.y));
    a[2] = cmul(a[2], make_float2(v0.z, v0.w));
    a[3] = cmul(a[3], make_float2(v1.x, v1.y));
    a[4] = cmul(a[4], make_float2(v1.z, v1.w));
    a[5] = cmul(a[5], make_float2(v2.x, v2.y));
    a[6] = cmul(a[6], make_float2(v2.z, v2.w));
    a[7] = cmul(a[7], make_float2(v3.x, v3.y));
}

// V[k] from Zk, Zn=Z[(N-k) mod N] (Hermitian split; positive scale dropped)
__device__ __forceinline__ float2 vval(float2 Zk, float2 Zn) {
    const float Xr = Zk.x + Zn.x;
    const float Xi = Zk.y - Zn.y;
    const float Yr = Zk.y + Zn.y;
    const float Yi = Zn.x - Zk.x;
    return make_float2(Xr * Yr + Xi * Yi, Xi * Yr - Xr * Yi);
}

__global__ void __launch_bounds__(THREADS, 2)
batch_align_kernel(const float* __restrict__ x,
                   const float* __restrict__ xref,
                   float* __restrict__ out_aligned,
                   float* __restrict__ out_inds) {
    const int row = blockIdx.x;
    const int tid = threadIdx.x;
    const float* xr = x    + (size_t)row * FFT_N;
    const float* yr = xref + (size_t)row * FFT_N;

    extern __shared__ float smem_raw[];
    float2* sb   = (float2*)smem_raw;            // PADN float2
    float*  wv   = (float*)(sb + PADN);          // 16
    int*    wi   = (int*)(wv + 16);              // 16
    int*    fnd  = (int*)(wi + 16);              // 1

    const float TH1 = -2.0f * (float)M_PI / (float)FFT_N;

    // Strength-reduced bases (PAD affine along every pattern):
    //   PAD(tid + 512q) = PAD(tid) + 544q ;  PAD(i + 4096) = PAD(i) + 4352
    float2* const pl = sb + PAD(tid);            // lower half, stride-512 base
    float2* const pu = pl + UPO;                 // upper half, stride-512 base

    // ---------- pass 0 of FFT1 ----------
    {
        float2 a[16];
        #pragma unroll
        for (int q = 0; q < 16; q++) {
            const int k = tid + q * 512;
            a[q] = make_float2(xr[k], yr[k]);
        }
        bfly16(a);
        stage_twiddle0(a, tid, TH1);
        float4* dst = (float4*)&sb[PAD(tid << 4)];
        #pragma unroll
        for (int j = 0; j < 8; j++) {
            const float2 lo = a[SLOT[2*j]], hi = a[SLOT[2*j+1]];
            dst[j] = make_float4(lo.x, lo.y, hi.x, hi.y);
        }
    }
    __syncthreads();

    // ---------- FFT1 pass 1 (const table A) ----------
    {
        float2 a[16];
        #pragma unroll
        for (int q = 0; q < 16; q++) a[q] = pl[544 * q];
        bfly16(a);
        apply_tw15(a, TBL_A + (tid & ~15));
        __syncthreads();
        float2* const ps = sb + PAD(((tid & ~15) << 4) + (tid & 15));
        #pragma unroll
        for (int q = 0; q < 16; q++)
            ps[16*q + 2*(q >> 1)] = a[SLOT[q]];
    }
    __syncthreads();

    // ---------- FFT1 pass 2 (const table B; j=0 half twiddle-free) ----------
    {
        float2 a[16];
        #pragma unroll
        for (int q = 0; q < 16; q++) a[q] = pl[544 * q];
        bfly16(a);
        if (tid >= 256) apply_tw15(a, TBL_B);
        __syncthreads();
        float2* const ps = sb + PAD(((tid & ~255) << 4) + (tid & 255));
        #pragma unroll
        for (int q = 0; q < 16; q++)
            ps[272 * q] = a[SLOT[q]];
    }
    __syncthreads();

    // ---------- MEGA-FUSED: radix-2 + Hermitian mult + irfft repack + FFT2 pass0 ----
    {
        float sn0, cs0;
        __sincosf(TH1 * (float)tid, &sn0, &cs0);
        const float2 wt = make_float2(cs0, sn0);

        const float C  = 0.70710678118654752f;
        const float c8 = 0.92387953251128676f;
        const float s8 = 0.38268343236508977f;
        const float2 ROT[8] = {
            make_float2( 1.f,  0.f), make_float2( c8, -s8),
            make_float2(  C,  -C ), make_float2( s8, -c8),
            make_float2( 0.f, -1.f), make_float2(-s8, -c8),
            make_float2( -C,  -C ), make_float2(-c8, -s8)
        };

        const int i2_0 = (HALF_N - tid) & (HALF_N - 1);
        float2 q[8];
        #pragma unroll
        for (int i = 0; i < 8; i++) {
            const float2 lo1 = pl[544 * i];
            const float2 hi1 = pl[544 * i + 4352];
            const float2 Zm  = cadd(lo1, hi1);
            const float2 Zm4 = csub(lo1, hi1);
            const int idx2 = (i2_0 - 512 * i) & (HALF_N - 1);
            const int pd = PAD(idx2);
            const float2 lo2 = sb[pd];
            const float2 hi2 = sb[pd + 4352];
            float2 Z4m = cadd(lo2, hi2);
            float2 Z8m = csub(lo2, hi2);
            if (i == 0 && tid == 0) { const float2 t = Z4m; Z4m = Z8m; Z8m = t; }
            const float2 Vm = vval(Zm,  Z8m);
            const float2 Vh = vval(Zm4, Z4m);
            const float2 P = cadd(Vm, Vh);
            const float2 D = csub(Vm, Vh);
            const float2 R = cmul(cmul(D, wt), ROT[i]);
            q[i] = make_float2(P.x - R.y, P.y + R.x);
        }
        __syncthreads();

        // FFT2 pass0 (m=1) on registers
        bfly8(q);
        const float2 w1 = cmul(wt, wt);
        const float2 w2 = cmul(w1, w1);
        const float2 w3 = cmul(w2, w1);
        const float2 w4 = cmul(w2, w2);
        q[1] = cmul(q[1], w1);
        q[2] = cmul(q[2], w2);
        q[3] = cmul(q[3], w3);
        q[4] = cmul(q[4], w4);
        q[5] = cmul(q[5], cmul(w4, w1));
        q[6] = cmul(q[6], cmul(w4, w2));
        q[7] = cmul(q[7], cmul(w4, w3));
        float4* dst = (float4*)&sb[UPO + PAD(tid << 3)];
        #pragma unroll
        for (int j = 0; j < 4; j++)
            dst[j] = make_float4(q[2*j].x, q[2*j].y, q[2*j+1].x, q[2*j+1].y);
    }
    __syncthreads();

    // ---------- FFT2 remaining passes (m=8, m=64, m=512) ----------
    // m=8: upper -> lower, const table C
    {
        float2 a[8];
        #pragma unroll
        for (int q = 0; q < 8; q++) a[q] = pu[544 * q];
        bfly8(a);
        apply_tw7(a, TBL_C + (tid & ~7));
        float2* const ps = sb + PAD(((tid & ~7) << 3) + (tid & 7));
        #pragma unroll
        for (int q = 0; q < 8; q++)
            ps[8*q + 2*(q >> 2)] = a[q];
    }
    __syncthreads();
    // m=64: lower -> upper, const table D
    {
        float2 a[8];
        #pragma unroll
        for (int q = 0; q < 8; q++) a[q] = pl[544 * q];
        bfly8(a);
        apply_tw7(a, TBL_D + ((tid >> 6) << 3));
        float2* const ps = sb + UPO + PAD(((tid & ~63) << 3) + (tid & 63));
        #pragma unroll
        for (int q = 0; q < 8; q++)
            ps[68 * q] = a[q];
    }
    __syncthreads();

    // m=512: twiddle-free, argmax from registers.
    float best = -INFINITY;
    int   bidx = 0x7fffffff;
    {
        float2 a[8];
        #pragma unroll
        for (int q = 0; q < 8; q++) a[q] = pu[544 * q];
        bfly8(a);
        #pragma unroll
        for (int q = 0; q < 8; q++) {
            const int n = tid + q * 512;
            if (a[q].x > best) { best = a[q].x; bidx = 2 * n; }
            if (a[q].y > best) { best = a[q].y; bidx = 2 * n + 1; }
        }
    }

    // ---------- argmax reduction (first-index tiebreak) ----------
    const int lane = tid & 31, wid = tid >> 5;
    #pragma unroll
    for (int off = 16; off > 0; off >>= 1) {
        const float v2 = __shfl_down_sync(0xffffffffu, best, off);
        const int   i2 = __shfl_down_sync(0xffffffffu, bidx, off);
        if (v2 > best || (v2 == best && i2 < bidx)) { best = v2; bidx = i2; }
    }
    if (lane == 0) { wv[wid] = best; wi[wid] = bidx; }
    __syncthreads();
    if (wid == 0) {
        float b2 = (lane < 16) ? wv[lane] : -INFINITY;
        int   j2 = (lane < 16) ? wi[lane] : 0x7fffffff;
        #pragma unroll
        for (int off = 8; off > 0; off >>= 1) {
            const float v2 = __shfl_down_sync(0xffffffffu, b2, off);
            const int   i2 = __shfl_down_sync(0xffffffffu, j2, off);
            if (v2 > b2 || (v2 == b2 && i2 < j2)) { b2 = v2; j2 = i2; }
        }
        if (lane == 0) *fnd = j2;
    }
    __syncthreads();
    const int ind = *fnd;

    // ---------- circular roll (float4 stores, strength-reduced gather) ----------
    float4* out4 = (float4*)(out_aligned + (size_t)row * FFT_N);
    const int k0 = (4 * tid - ind) & (FFT_N - 1);
    #pragma unroll
    for (int i = 0; i < 4; i++) {
        const int b = (k0 + 2048 * i) & (FFT_N - 1);
        float4 v;
        v.x = xr[b];
        v.y = xr[(b + 1) & (FFT_N - 1)];
        v.z = xr[(b + 2) & (FFT_N - 1)];
        v.w = xr[(b + 3) & (FFT_N - 1)];
        out4[tid + i * 512] = v;
    }
    if (tid == 0)
        out_inds[row] = (float)ind;
}

extern "C" void kernel_launch(void* const* d_in, const int* in_sizes, int n_in,
                              void* d_out, int out_size) {
    const float* x    = (const float*)d_in[0];
    const float* xref = (const float*)d_in[1];
    float* out = (float*)d_out;

    const int rows = in_sizes[0] / FFT_N;    // 2048
    float* out_aligned = out;
    float* out_inds    = out + (size_t)rows * FFT_N;

    const size_t smem = PADN * sizeof(float2)
                      + 16 * sizeof(float) + 17 * sizeof(int);
    cudaFuncSetAttribute(batch_align_kernel,
                         cudaFuncAttributeMaxDynamicSharedMemorySize, (int)smem);
    batch_align_kernel<<<rows, THREADS, smem>>>(x, xref, out_aligned, out_inds);
}

// round 15
// speedup vs baseline: 1.1088x; 1.1088x over previous
#include <cuda_runtime.h>
#include <math.h>

#define FFT_N    8192
#define HALF_N   4096
#define THREADS  512
// alignment-preserving pad: +2 float2 (16B) per 32 float2.
#define PAD(i)   ((i) + (((i) >> 5) << 1))
#define PADN     (FFT_N + (FFT_N >> 4))      // 8704 float2
#define UPO      4352                         // PAD(4096)

// twiddle table: rows padded to float4 boundaries
#define TBL_A    0      // FFT1 p1: 32 rows x 16 (q=1..15 used)   (512)
#define TBL_B    512    // FFT1 p2: 1 row x 16                    (16)
#define TBL_C    528    // FFT2 m=8:  64 rows x 8 (q=1..7 used)   (512)
#define TBL_D    1040   // FFT2 m=64:  8 rows x 8                 (64)
#define TBL_TOT  1104

__device__ constexpr int SLOT[16] = {0,4,8,12, 1,5,9,13, 2,6,10,14, 3,7,11,15};

__device__ __forceinline__ float2 cadd(float2 a, float2 b){ return make_float2(a.x+b.x, a.y+b.y); }
__device__ __forceinline__ float2 csub(float2 a, float2 b){ return make_float2(a.x-b.x, a.y-b.y); }
__device__ __forceinline__ float2 cmul(float2 a, float2 b){
    return make_float2(a.x*b.x - a.y*b.y, a.x*b.y + a.y*b.x);
}
__device__ __forceinline__ float2 cmul_negi(float2 a){ return make_float2(a.y, -a.x); }

// In-place 16-point DFT (e^-). Output y[q] at a[SLOT[q]].
__device__ __forceinline__ void bfly16(float2 a[16]) {
    const float C  = 0.70710678118654752f;
    const float c8 = 0.92387953251128676f;
    const float s8 = 0.38268343236508977f;
    #pragma unroll
    for (int n0 = 0; n0 < 4; n0++) {
        float2 p0 = a[n0], p1 = a[n0+4], p2 = a[n0+8], p3 = a[n0+12];
        float2 t0 = cadd(p0,p2), t1 = csub(p0,p2);
        float2 t2 = cadd(p1,p3);
        float2 t3 = cmul_negi(csub(p1,p3));
        a[n0]    = cadd(t0,t2);
        a[n0+4]  = cadd(t1,t3);
        a[n0+8]  = csub(t0,t2);
        a[n0+12] = csub(t1,t3);
    }
    { float2 v=a[5];  a[5]  = make_float2( c8*v.x + s8*v.y,  c8*v.y - s8*v.x); }
    { float2 v=a[6];  a[6]  = make_float2( C*(v.x+v.y),      C*(v.y-v.x)); }
    { float2 v=a[7];  a[7]  = make_float2( s8*v.x + c8*v.y,  s8*v.y - c8*v.x); }
    { float2 v=a[9];  a[9]  = make_float2( C*(v.x+v.y),      C*(v.y-v.x)); }
    { float2 v=a[10]; a[10] = make_float2( v.y, -v.x); }
    { float2 v=a[11]; a[11] = make_float2( C*(v.y-v.x),     -C*(v.x+v.y)); }
    { float2 v=a[13]; a[13] = make_float2( s8*v.x + c8*v.y,  s8*v.y - c8*v.x); }
    { float2 v=a[14]; a[14] = make_float2( C*(v.y-v.x),     -C*(v.x+v.y)); }
    { float2 v=a[15]; a[15] = make_float2(-c8*v.x - s8*v.y,  s8*v.x - c8*v.y); }
    #pragma unroll
    for (int k0 = 0; k0 < 4; k0++) {
        float2 p0 = a[4*k0], p1 = a[4*k0+1], p2 = a[4*k0+2], p3 = a[4*k0+3];
        float2 t0 = cadd(p0,p2), t1 = csub(p0,p2);
        float2 t2 = cadd(p1,p3);
        float2 t3 = cmul_negi(csub(p1,p3));
        a[4*k0]   = cadd(t0,t2);
        a[4*k0+1] = cadd(t1,t3);
        a[4*k0+2] = csub(t0,t2);
        a[4*k0+3] = csub(t1,t3);
    }
}

// 8-point DFT, natural-order outputs in place.
__device__ __forceinline__ void bfly8(float2 a[8]) {
    const float C = 0.70710678118654752f;
    float2 u0 = cadd(a[0], a[4]), u1 = csub(a[0], a[4]);
    float2 u2 = cadd(a[2], a[6]), u3 = csub(a[2], a[6]);
    float2 E0 = cadd(u0, u2), E2 = csub(u0, u2);
    float2 mi3 = cmul_negi(u3);
    float2 E1 = cadd(u1, mi3), E3 = csub(u1, mi3);
    float2 v0 = cadd(a[1], a[5]), v1 = csub(a[1], a[5]);
    float2 v2 = cadd(a[3], a[7]), v3 = csub(a[3], a[7]);
    float2 O0 = cadd(v0, v2), O2 = csub(v0, v2);
    float2 ni3 = cmul_negi(v3);
    float2 O1 = cadd(v1, ni3), O3 = csub(v1, ni3);
    float2 w1O = make_float2(C*(O1.x+O1.y), C*(O1.y-O1.x));
    float2 w2O = cmul_negi(O2);
    float2 w3O = make_float2(C*(O3.y-O3.x), -C*(O3.x+O3.y));
    a[0]=cadd(E0,O0);  a[4]=csub(E0,O0);
    a[1]=cadd(E1,w1O); a[5]=csub(E1,w1O);
    a[2]=cadd(E2,w2O); a[6]=csub(E2,w2O);
    a[3]=cadd(E3,w3O); a[7]=csub(E3,w3O);
}

// Tree-structured twiddle generation + apply (FFT1 pass 0 only).
__device__ __forceinline__ void stage_twiddle0(float2 a[16], int jm, float theta_step) {
    float sn, cs;
    __sincosf(theta_step * (float)jm, &sn, &cs);
    const float2 w1 = make_float2(cs, sn);
    const float2 w2 = cmul(w1, w1);
    const float2 w3 = cmul(w2, w1);
    const float2 w4 = cmul(w2, w2);
    const float2 w5 = cmul(w4, w1);
    const float2 w6 = cmul(w4, w2);
    const float2 w7 = cmul(w4, w3);
    const float2 w8 = cmul(w4, w4);
    a[SLOT[1]]  = cmul(a[SLOT[1]],  w1);
    a[SLOT[2]]  = cmul(a[SLOT[2]],  w2);
    a[SLOT[3]]  = cmul(a[SLOT[3]],  w3);
    a[SLOT[4]]  = cmul(a[SLOT[4]],  w4);
    a[SLOT[5]]  = cmul(a[SLOT[5]],  w5);
    a[SLOT[6]]  = cmul(a[SLOT[6]],  w6);
    a[SLOT[7]]  = cmul(a[SLOT[7]],  w7);
    a[SLOT[8]]  = cmul(a[SLOT[8]],  w8);
    a[SLOT[9]]  = cmul(a[SLOT[9]],  cmul(w8, w1));
    a[SLOT[10]] = cmul(a[SLOT[10]], cmul(w8, w2));
    a[SLOT[11]] = cmul(a[SLOT[11]], cmul(w8, w3));
    a[SLOT[12]] = cmul(a[SLOT[12]], cmul(w8, w4));
    a[SLOT[13]] = cmul(a[SLOT[13]], cmul(w8, w5));
    a[SLOT[14]] = cmul(a[SLOT[14]], cmul(w8, w6));
    a[SLOT[15]] = cmul(a[SLOT[15]], cmul(w8, w7));
}

// V[k] from Zk, Zn=Z[(N-k) mod N] (Hermitian split; positive scale dropped)
__device__ __forceinline__ float2 vval(float2 Zk, float2 Zn) {
    const float Xr = Zk.x + Zn.x;
    const float Xi = Zk.y - Zn.y;
    const float Yr = Zk.y + Zn.y;
    const float Yi = Zn.x - Zk.x;
    return make_float2(Xr * Yr + Xi * Yi, Xi * Yr - Xr * Yi);
}

__global__ void __launch_bounds__(THREADS, 2)
batch_align_kernel(const float* __restrict__ x,
                   const float* __restrict__ xref,
                   float* __restrict__ out_aligned,
                   float* __restrict__ out_inds) {
    const int row = blockIdx.x;
    const int tid = threadIdx.x;
    const float* xr = x    + (size_t)row * FFT_N;
    const float* yr = xref + (size_t)row * FFT_N;

    extern __shared__ float smem_raw[];
    float2* sb   = (float2*)smem_raw;            // PADN float2
    float2* twid = sb + PADN;                    // TBL_TOT float2 (16B aligned)
    float*  wv   = (float*)(twid + TBL_TOT);     // 16
    int*    wi   = (int*)(wv + 16);              // 16
    int*    fnd  = (int*)(wi + 16);              // 1

    const float TH1 = -2.0f * (float)M_PI / (float)FFT_N;
    const float TH2 = -2.0f * (float)M_PI / (float)HALF_N;

    // Strength-reduced bases: PAD(tid + 512q) = PAD(tid) + 544q ; PAD(i+4096)=PAD(i)+4352
    float2* const pl = sb + PAD(tid);            // lower half, stride-512 base
    float2* const pu = pl + UPO;                 // upper half, stride-512 base

    // ---------- pass 0 of FFT1 + twiddle-table fill (overlapped) ----------
    {
        float2 a[16];
        #pragma unroll
        for (int q = 0; q < 16; q++) {
            const int k = tid + q * 512;
            a[q] = make_float2(xr[k], yr[k]);     // LDGs issued first
        }
        #pragma unroll
        for (int r = 0; r < 3; r++) {
            const int e = tid + r * THREADS;
            if (e < TBL_TOT) {
                float ang;
                if (e < TBL_B) {
                    const int j = e >> 4, q = (e & 15) + 1;
                    ang = TH1 * (float)(16 * j * q);
                } else if (e < TBL_C) {
                    const int q = e - TBL_B + 1;
                    ang = TH1 * (float)(256 * q);
                } else if (e < TBL_D) {
                    const int r2 = e - TBL_C;
                    const int j = r2 >> 3, q = (r2 & 7) + 1;
                    ang = TH2 * (float)(8 * j * q);
                } else {
                    const int r2 = e - TBL_D;
                    const int j = r2 >> 3, q = (r2 & 7) + 1;
                    ang = TH2 * (float)(64 * j * q);
                }
                float sn, cs; __sincosf(ang, &sn, &cs);
                twid[e] = make_float2(cs, sn);
            }
        }
        bfly16(a);
        stage_twiddle0(a, tid, TH1);
        float4* dst = (float4*)&sb[PAD(tid << 4)];
        #pragma unroll
        for (int j = 0; j < 8; j++) {
            const float2 lo = a[SLOT[2*j]], hi = a[SLOT[2*j+1]];
            dst[j] = make_float4(lo.x, lo.y, hi.x, hi.y);
        }
    }
    __syncthreads();

    // ---------- FFT1 pass 1 (table A; twiddles loaded BEFORE butterfly) ----------
    {
        // hoist twiddle loads so their LDS latency hides under bfly16
        const float4* w4 = (const float4*)&twid[TBL_A + (tid & ~15)];
        float4 wreg[8];
        #pragma unroll
        for (int h = 0; h < 8; h++) wreg[h] = w4[h];

        float2 a[16];
        #pragma unroll
        for (int q = 0; q < 16; q++) a[q] = pl[544 * q];
        bfly16(a);
        #pragma unroll
        for (int h = 0; h < 8; h++) {
            a[SLOT[2*h+1]] = cmul(a[SLOT[2*h+1]], make_float2(wreg[h].x, wreg[h].y));
            if (2*h+2 < 16)
                a[SLOT[2*h+2]] = cmul(a[SLOT[2*h+2]], make_float2(wreg[h].z, wreg[h].w));
        }
        __syncthreads();
        float2* const ps = sb + PAD(((tid & ~15) << 4) + (tid & 15));
        #pragma unroll
        for (int q = 0; q < 16; q++)
            ps[16*q + 2*(q >> 1)] = a[SLOT[q]];
    }
    __syncthreads();

    // ---------- FFT1 pass 2 (table B; j=0 half twiddle-free) ----------
    {
        const float4* w4 = (const float4*)&twid[TBL_B];
        float4 wreg[8];
        #pragma unroll
        for (int h = 0; h < 8; h++) wreg[h] = w4[h];

        float2 a[16];
        #pragma unroll
        for (int q = 0; q < 16; q++) a[q] = pl[544 * q];
        bfly16(a);
        if (tid >= 256) {
            #pragma unroll
            for (int h = 0; h < 8; h++) {
                a[SLOT[2*h+1]] = cmul(a[SLOT[2*h+1]], make_float2(wreg[h].x, wreg[h].y));
                if (2*h+2 < 16)
                    a[SLOT[2*h+2]] = cmul(a[SLOT[2*h+2]], make_float2(wreg[h].z, wreg[h].w));
            }
        }
        __syncthreads();
        float2* const ps = sb + PAD(((tid & ~255) << 4) + (tid & 255));
        #pragma unroll
        for (int q = 0; q < 16; q++)
            ps[272 * q] = a[SLOT[q]];
    }
    __syncthreads();

    // ---------- MEGA-FUSED: radix-2 + Hermitian mult + irfft repack + FFT2 pass0 ----
    {
        float sn0, cs0;
        __sincosf(TH1 * (float)tid, &sn0, &cs0);
        const float2 wt = make_float2(cs0, sn0);

        const float C  = 0.70710678118654752f;
        const float c8 = 0.92387953251128676f;
        const float s8 = 0.38268343236508977f;
        const float2 ROT[8] = {
            make_float2( 1.f,  0.f), make_float2( c8, -s8),
            make_float2(  C,  -C ), make_float2( s8, -c8),
            make_float2( 0.f, -1.f), make_float2(-s8, -c8),
            make_float2( -C,  -C ), make_float2(-c8, -s8)
        };

        // mirror base: for tid>0, idx2 = 4096 - tid - 512 i  (no wrap for i<8);
        // PAD affine -> base pointer minus 544 i. tid==0 handled at i==0 only.
        const int pm_base = PAD(HALF_N - tid);   // tid=0 -> PAD(4096)=4352 (used for i>=1)
        float2 q[8];
        #pragma unroll
        for (int i = 0; i < 8; i++) {
            const float2 lo1 = pl[544 * i];
            const float2 hi1 = pl[544 * i + 4352];
            const float2 Zm  = cadd(lo1, hi1);
            const float2 Zm4 = csub(lo1, hi1);
            int pd = pm_base - 544 * i;
            if (i == 0 && tid == 0) pd = 0;      // idx2 = 0 corner
            const float2 lo2 = sb[pd];
            const float2 hi2 = sb[pd + 4352];
            float2 Z4m = cadd(lo2, hi2);
            float2 Z8m = csub(lo2, hi2);
            if (i == 0 && tid == 0) { const float2 t = Z4m; Z4m = Z8m; Z8m = t; }
            const float2 Vm = vval(Zm,  Z8m);
            const float2 Vh = vval(Zm4, Z4m);
            const float2 P = cadd(Vm, Vh);
            const float2 D = csub(Vm, Vh);
            const float2 R = cmul(cmul(D, wt), ROT[i]);
            q[i] = make_float2(P.x - R.y, P.y + R.x);
        }
        __syncthreads();

        // FFT2 pass0 (m=1) on registers
        bfly8(q);
        const float2 w1 = cmul(wt, wt);
        const float2 w2 = cmul(w1, w1);
        const float2 w3 = cmul(w2, w1);
        const float2 w4 = cmul(w2, w2);
        q[1] = cmul(q[1], w1);
        q[2] = cmul(q[2], w2);
        q[3] = cmul(q[3], w3);
        q[4] = cmul(q[4], w4);
        q[5] = cmul(q[5], cmul(w4, w1));
        q[6] = cmul(q[6], cmul(w4, w2));
        q[7] = cmul(q[7], cmul(w4, w3));
        float4* dst = (float4*)&sb[UPO + PAD(tid << 3)];
        #pragma unroll
        for (int j = 0; j < 4; j++)
            dst[j] = make_float4(q[2*j].x, q[2*j].y, q[2*j+1].x, q[2*j+1].y);
    }
    __syncthreads();

    // ---------- FFT2 remaining passes (m=8, m=64, m=512) ----------
    // m=8: upper -> lower, table C
    {
        const float4* w4 = (const float4*)&twid[TBL_C + (tid & ~7)];
        float4 wr0 = w4[0], wr1 = w4[1], wr2 = w4[2], wr3 = w4[3];

        float2 a[8];
        #pragma unroll
        for (int q = 0; q < 8; q++) a[q] = pu[544 * q];
        bfly8(a);
        a[1] = cmul(a[1], make_float2(wr0.x, wr0.y));
        a[2] = cmul(a[2], make_float2(wr0.z, wr0.w));
        a[3] = cmul(a[3], make_float2(wr1.x, wr1.y));
        a[4] = cmul(a[4], make_float2(wr1.z, wr1.w));
        a[5] = cmul(a[5], make_float2(wr2.x, wr2.y));
        a[6] = cmul(a[6], make_float2(wr2.z, wr2.w));
        a[7] = cmul(a[7], make_float2(wr3.x, wr3.y));
        float2* const ps = sb + PAD(((tid & ~7) << 3) + (tid & 7));
        #pragma unroll
        for (int q = 0; q < 8; q++)
            ps[8*q + 2*(q >> 2)] = a[q];
    }
    __syncthreads();
    // m=64: lower -> upper, table D
    {
        const float4* w4 = (const float4*)&twid[TBL_D + ((tid >> 6) << 3)];
        float4 wr0 = w4[0], wr1 = w4[1], wr2 = w4[2], wr3 = w4[3];

        float2 a[8];
        #pragma unroll
        for (int q = 0; q < 8; q++) a[q] = pl[544 * q];
        bfly8(a);
        a[1] = cmul(a[1], make_float2(wr0.x, wr0.y));
        a[2] = cmul(a[2], make_float2(wr0.z, wr0.w));
        a[3] = cmul(a[3], make_float2(wr1.x, wr1.y));
        a[4] = cmul(a[4], make_float2(wr1.z, wr1.w));
        a[5] = cmul(a[5], make_float2(wr2.x, wr2.y));
        a[6] = cmul(a[6], make_float2(wr2.z, wr2.w));
        a[7] = cmul(a[7], make_float2(wr3.x, wr3.y));
        float2* const ps = sb + UPO + PAD(((tid & ~63) << 3) + (tid & 63));
        #pragma unroll
        for (int q = 0; q < 8; q++)
            ps[68 * q] = a[q];
    }
    __syncthreads();

    // m=512: twiddle-free, argmax from registers.
    float best = -INFINITY;
    int   bidx = 0x7fffffff;
    {
        float2 a[8];
        #pragma unroll
        for (int q = 0; q < 8; q++) a[q] = pu[544 * q];
        bfly8(a);
        #pragma unroll
        for (int q = 0; q < 8; q++) {
            const int n = tid + q * 512;
            if (a[q].x > best) { best = a[q].x; bidx = 2 * n; }
            if (a[q].y > best) { best = a[q].y; bidx = 2 * n + 1; }
        }
    }

    // ---------- argmax reduction (first-index tiebreak) ----------
    const int lane = tid & 31, wid = tid >> 5;
    #pragma unroll
    for (int off = 16; off > 0; off >>= 1) {
        const float v2 = __shfl_down_sync(0xffffffffu, best, off);
        const int   i2 = __shfl_down_sync(0xffffffffu, bidx, off);
        if (v2 > best || (v2 == best && i2 < bidx)) { best = v2; bidx = i2; }
    }
    if (lane == 0) { wv[wid] = best; wi[wid] = bidx; }
    __syncthreads();
    if (wid == 0) {
        float b2 = (lane < 16) ? wv[lane] : -INFINITY;
        int   j2 = (lane < 16) ? wi[lane] : 0x7fffffff;
        #pragma unroll
        for (int off = 8; off > 0; off >>= 1) {
            const float v2 = __shfl_down_sync(0xffffffffu, b2, off);
            const int   i2 = __shfl_down_sync(0xffffffffu, j2, off);
            if (v2 > b2 || (v2 == b2 && i2 < j2)) { b2 = v2; j2 = i2; }
        }
        if (lane == 0) *fnd = j2;
    }
    __syncthreads();
    const int ind = *fnd;

    // ---------- circular roll (float4 stores, strength-reduced gather) ----------
    float4* out4 = (float4*)(out_aligned + (size_t)row * FFT_N);
    const int k0 = (4 * tid - ind) & (FFT_N - 1);
    #pragma unroll
    for (int i = 0; i < 4; i++) {
        const int b = (k0 + 2048 * i) & (FFT_N - 1);
        float4 v;
        v.x = xr[b];
        v.y = xr[(b + 1) & (FFT_N - 1)];
        v.z = xr[(b + 2) & (FFT_N - 1)];
        v.w = xr[(b + 3) & (FFT_N - 1)];
        out4[tid + i * 512] = v;
    }
    if (tid == 0)
        out_inds[row] = (float)ind;
}

extern "C" void kernel_launch(void* const* d_in, const int* in_sizes, int n_in,
                              void* d_out, int out_size) {
    const float* x    = (const float*)d_in[0];
    const float* xref = (const float*)d_in[1];
    float* out = (float*)d_out;

    const int rows = in_sizes[0] / FFT_N;    // 2048
    float* out_aligned = out;
    float* out_inds    = out + (size_t)rows * FFT_N;

    const size_t smem = PADN * sizeof(float2)
                      + TBL_TOT * sizeof(float2)
                      + 16 * sizeof(float) + 17 * sizeof(int);
    cudaFuncSetAttribute(batch_align_kernel,
                         cudaFuncAttributeMaxDynamicSharedMemorySize, (int)smem);
    batch_align_kernel<<<rows, THREADS, smem>>>(x, xref, out_aligned, out_inds);
}

// round 17
// speedup vs baseline: 1.2114x; 1.0925x over previous
#include <cuda_runtime.h>
#include <math.h>

#define FFT_N    8192
#define HALF_N   4096
#define THREADS  512
// alignment-preserving pad: +2 float2 (16B) per 32 float2.
#define PAD(i)   ((i) + (((i) >> 5) << 1))
#define PADN     (FFT_N + (FFT_N >> 4))      // 8704 float2
#define UPO      4352                         // PAD(4096)

// twiddle tables (float2 entries; rows padded to 16 for float4 loads)
#define TBL_A    0      // FFT1 p1: 32 rows x 16 (q=1..15 used)
#define TBL_B    512    // FFT1 p2: 1 row x 16
#define TBL_E    528    // FFT2 p1: 16 rows x 16 (TH2, j=16*(t>>4))
#define TBL_TOT  784

__device__ constexpr int SLOT[16] = {0,4,8,12, 1,5,9,13, 2,6,10,14, 3,7,11,15};

__device__ __forceinline__ float2 cadd(float2 a, float2 b){ return make_float2(a.x+b.x, a.y+b.y); }
__device__ __forceinline__ float2 csub(float2 a, float2 b){ return make_float2(a.x-b.x, a.y-b.y); }
__device__ __forceinline__ float2 cmul(float2 a, float2 b){
    return make_float2(a.x*b.x - a.y*b.y, a.x*b.y + a.y*b.x);
}
__device__ __forceinline__ float2 cmul_negi(float2 a){ return make_float2(a.y, -a.x); }

// In-place 16-point DFT (e^-). Output y[q] at a[SLOT[q]].
__device__ __forceinline__ void bfly16(float2 a[16]) {
    const float C  = 0.70710678118654752f;
    const float c8 = 0.92387953251128676f;
    const float s8 = 0.38268343236508977f;
    #pragma unroll
    for (int n0 = 0; n0 < 4; n0++) {
        float2 p0 = a[n0], p1 = a[n0+4], p2 = a[n0+8], p3 = a[n0+12];
        float2 t0 = cadd(p0,p2), t1 = csub(p0,p2);
        float2 t2 = cadd(p1,p3);
        float2 t3 = cmul_negi(csub(p1,p3));
        a[n0]    = cadd(t0,t2);
        a[n0+4]  = cadd(t1,t3);
        a[n0+8]  = csub(t0,t2);
        a[n0+12] = csub(t1,t3);
    }
    { float2 v=a[5];  a[5]  = make_float2( c8*v.x + s8*v.y,  c8*v.y - s8*v.x); }
    { float2 v=a[6];  a[6]  = make_float2( C*(v.x+v.y),      C*(v.y-v.x)); }
    { float2 v=a[7];  a[7]  = make_float2( s8*v.x + c8*v.y,  s8*v.y - c8*v.x); }
    { float2 v=a[9];  a[9]  = make_float2( C*(v.x+v.y),      C*(v.y-v.x)); }
    { float2 v=a[10]; a[10] = make_float2( v.y, -v.x); }
    { float2 v=a[11]; a[11] = make_float2( C*(v.y-v.x),     -C*(v.x+v.y)); }
    { float2 v=a[13]; a[13] = make_float2( s8*v.x + c8*v.y,  s8*v.y - c8*v.x); }
    { float2 v=a[14]; a[14] = make_float2( C*(v.y-v.x),     -C*(v.x+v.y)); }
    { float2 v=a[15]; a[15] = make_float2(-c8*v.x - s8*v.y,  s8*v.x - c8*v.y); }
    #pragma unroll
    for (int k0 = 0; k0 < 4; k0++) {
        float2 p0 = a[4*k0], p1 = a[4*k0+1], p2 = a[4*k0+2], p3 = a[4*k0+3];
        float2 t0 = cadd(p0,p2), t1 = csub(p0,p2);
        float2 t2 = cadd(p1,p3);
        float2 t3 = cmul_negi(csub(p1,p3));
        a[4*k0]   = cadd(t0,t2);
        a[4*k0+1] = cadd(t1,t3);
        a[4*k0+2] = csub(t0,t2);
        a[4*k0+3] = csub(t1,t3);
    }
}

// Apply stage twiddles w^q given w1 (tree-structured powers).
__device__ __forceinline__ void stage_twiddle_w(float2 a[16], float2 w1) {
    const float2 w2 = cmul(w1, w1);
    const float2 w3 = cmul(w2, w1);
    const float2 w4 = cmul(w2, w2);
    const float2 w5 = cmul(w4, w1);
    const float2 w6 = cmul(w4, w2);
    const float2 w7 = cmul(w4, w3);
    const float2 w8 = cmul(w4, w4);
    a[SLOT[1]]  = cmul(a[SLOT[1]],  w1);
    a[SLOT[2]]  = cmul(a[SLOT[2]],  w2);
    a[SLOT[3]]  = cmul(a[SLOT[3]],  w3);
    a[SLOT[4]]  = cmul(a[SLOT[4]],  w4);
    a[SLOT[5]]  = cmul(a[SLOT[5]],  w5);
    a[SLOT[6]]  = cmul(a[SLOT[6]],  w6);
    a[SLOT[7]]  = cmul(a[SLOT[7]],  w7);
    a[SLOT[8]]  = cmul(a[SLOT[8]],  w8);
    a[SLOT[9]]  = cmul(a[SLOT[9]],  cmul(w8, w1));
    a[SLOT[10]] = cmul(a[SLOT[10]], cmul(w8, w2));
    a[SLOT[11]] = cmul(a[SLOT[11]], cmul(w8, w3));
    a[SLOT[12]] = cmul(a[SLOT[12]], cmul(w8, w4));
    a[SLOT[13]] = cmul(a[SLOT[13]], cmul(w8, w5));
    a[SLOT[14]] = cmul(a[SLOT[14]], cmul(w8, w6));
    a[SLOT[15]] = cmul(a[SLOT[15]], cmul(w8, w7));
}

// 15-twiddle apply from a 16-entry table row, float4 loads (R13 style)
__device__ __forceinline__ void apply_tw15(float2 a[16], const float2* wrow) {
    const float4* w4 = (const float4*)wrow;
    float2 w[16];
    #pragma unroll
    for (int h = 0; h < 8; h++) {
        const float4 v = w4[h];
        w[2*h]   = make_float2(v.x, v.y);
        w[2*h+1] = make_float2(v.z, v.w);
    }
    #pragma unroll
    for (int q = 1; q < 16; q++) a[SLOT[q]] = cmul(a[SLOT[q]], w[q-1]);
}

// V[k] from Zk, Zn=Z[(N-k) mod N] (Hermitian split; positive scale dropped)
__device__ __forceinline__ float2 vval(float2 Zk, float2 Zn) {
    const float Xr = Zk.x + Zn.x;
    const float Xi = Zk.y - Zn.y;
    const float Yr = Zk.y + Zn.y;
    const float Yi = Zn.x - Zk.x;
    return make_float2(Xr * Yr + Xi * Yi, Xi * Yr - Xr * Yi);
}

__global__ void __launch_bounds__(THREADS, 2)
batch_align_kernel(const float* __restrict__ x,
                   const float* __restrict__ xref,
                   float* __restrict__ out_aligned,
                   float* __restrict__ out_inds) {
    const int row = blockIdx.x;
    const int tid = threadIdx.x;
    const float* xr = x    + (size_t)row * FFT_N;
    const float* yr = xref + (size_t)row * FFT_N;

    extern __shared__ float smem_raw[];
    float2* sb   = (float2*)smem_raw;            // PADN float2
    float2* twid = sb + PADN;                    // TBL_TOT float2 (16B aligned)
    float*  wv   = (float*)(twid + TBL_TOT);     // 16
    int*    wi   = (int*)(wv + 16);              // 16
    int*    fnd  = (int*)(wi + 16);              // 1

    const float TH1 = -2.0f * (float)M_PI / (float)FFT_N;
    const float TH2 = -2.0f * (float)M_PI / (float)HALF_N;

    // Strength-reduced bases: PAD(t + 512q) = PAD(t) + 544q ; PAD(i+4096)=PAD(i)+4352
    float2* const pl = sb + PAD(tid);            // stride-512 base (FFT1)

    // ---------- FFT1 pass 0 + twiddle-table fill (overlapped) ----------
    {
        float2 a[16];
        #pragma unroll
        for (int q = 0; q < 16; q++) {
            const int k = tid + q * 512;
            a[q] = make_float2(xr[k], yr[k]);     // LDGs issued first
        }
        #pragma unroll
        for (int r = 0; r < 2; r++) {
            const int e = tid + r * THREADS;
            if (e < TBL_TOT) {
                float ang;
                if (e < TBL_B) {                         // A: 32 rows x 16, TH1
                    const int j = e >> 4, q = (e & 15) + 1;
                    ang = TH1 * (float)(16 * j * q);
                } else if (e < TBL_E) {                  // B: 1 row x 16, TH1
                    const int q = e - TBL_B + 1;
                    ang = TH1 * (float)(256 * q);
                } else {                                 // E: 16 rows x 16, TH2
                    const int r2 = e - TBL_E;
                    const int j = r2 >> 4, q = (r2 & 15) + 1;
                    ang = TH2 * (float)(16 * j * q);
                }
                float sn, cs; __sincosf(ang, &sn, &cs);
                twid[e] = make_float2(cs, sn);
            }
        }
        bfly16(a);
        {
            float sn, cs; __sincosf(TH1 * (float)tid, &sn, &cs);
            stage_twiddle_w(a, make_float2(cs, sn));
        }
        float4* dst = (float4*)&sb[PAD(tid << 4)];
        #pragma unroll
        for (int j = 0; j < 8; j++) {
            const float2 lo = a[SLOT[2*j]], hi = a[SLOT[2*j+1]];
            dst[j] = make_float4(lo.x, lo.y, hi.x, hi.y);
        }
    }
    __syncthreads();

    // ---------- FFT1 pass 1 (table A) ----------
    {
        float2 a[16];
        #pragma unroll
        for (int q = 0; q < 16; q++) a[q] = pl[544 * q];
        bfly16(a);
        apply_tw15(a, &twid[TBL_A + (tid & ~15)]);
        __syncthreads();
        float2* const ps = sb + PAD(((tid & ~15) << 4) + (tid & 15));
        #pragma unroll
        for (int q = 0; q < 16; q++)
            ps[16*q + 2*(q >> 1)] = a[SLOT[q]];
    }
    __syncthreads();

    // ---------- FFT1 pass 2 (table B; j=0 half twiddle-free) ----------
    {
        float2 a[16];
        #pragma unroll
        for (int q = 0; q < 16; q++) a[q] = pl[544 * q];
        bfly16(a);
        if (tid >= 256) apply_tw15(a, &twid[TBL_B]);
        __syncthreads();
        float2* const ps = sb + PAD(((tid & ~255) << 4) + (tid & 255));
        #pragma unroll
        for (int q = 0; q < 16; q++)
            ps[272 * q] = a[SLOT[q]];
    }
    __syncthreads();

    // ---------- MEGA-FUSED (256 threads): radix-2 + Hermitian mult + irfft repack
    //            + FFT2 pass0 (radix-16). Q[m] for m = tid + 256q, q = 0..15. ----
    float2 a2[16];
    float2 wt;
    const bool act = (tid < 256);
    if (act) {
        float sn0, cs0;
        __sincosf(TH1 * (float)tid, &sn0, &cs0);
        wt = make_float2(cs0, sn0);

        // ROT2[q] = e^{-i*pi*q/16}
        const float2 ROT2[16] = {
            make_float2( 1.00000000f,  0.00000000f), make_float2( 0.98078528f, -0.19509032f),
            make_float2( 0.92387953f, -0.38268343f), make_float2( 0.83146961f, -0.55557023f),
            make_float2( 0.70710678f, -0.70710678f), make_float2( 0.55557023f, -0.83146961f),
            make_float2( 0.38268343f, -0.92387953f), make_float2( 0.19509032f, -0.98078528f),
            make_float2( 0.00000000f, -1.00000000f), make_float2(-0.19509032f, -0.98078528f),
            make_float2(-0.38268343f, -0.92387953f), make_float2(-0.55557023f, -0.83146961f),
            make_float2(-0.70710678f, -0.70710678f), make_float2(-0.83146961f, -0.55557023f),
            make_float2(-0.92387953f, -0.38268343f), make_float2(-0.98078528f, -0.19509032f)
        };

        float2* const plq = sb + PAD(tid);       // stride-256 base: +272 per q
        const int pm_base = PAD(HALF_N - tid);   // mirror base (tid=0 -> 4352, used q>=1)
        #pragma unroll
        for (int q = 0; q < 16; q++) {
            const float2 lo1 = plq[272 * q];
            const float2 hi1 = plq[272 * q + 4352];
            const float2 Zm  = cadd(lo1, hi1);   // Z[m]
            const float2 Zm4 = csub(lo1, hi1);   // Z[m+4096]
            int pd = pm_base - 272 * q;
            if (q == 0 && tid == 0) pd = 0;      // m = 0 corner
            const float2 lo2 = sb[pd];
            const float2 hi2 = sb[pd + 4352];
            float2 Z4m = cadd(lo2, hi2);         // Z[4096-m]
            float2 Z8m = csub(lo2, hi2);         // Z[8192-m]
            if (q == 0 && tid == 0) { const float2 t = Z4m; Z4m = Z8m; Z8m = t; }
            const float2 Vm = vval(Zm,  Z8m);
            const float2 Vh = vval(Zm4, Z4m);
            const float2 P = cadd(Vm, Vh);
            const float2 D = csub(Vm, Vh);
            const float2 R = cmul(cmul(D, wt), ROT2[q]);  // D * e^{i*TH1*m}
            a2[q] = make_float2(P.x - R.y, P.y + R.x);    // Q[m] = P + i*R
        }
    }
    __syncthreads();        // all Z reads done before upper half is overwritten
    if (act) {
        // FFT2 pass0 (m=1) on registers; base twiddle w1 = wt^2 = e^{i*TH2*tid}
        bfly16(a2);
        stage_twiddle_w(a2, cmul(wt, wt));
        float4* dst = (float4*)&sb[UPO + PAD(tid << 4)];
        #pragma unroll
        for (int j = 0; j < 8; j++) {
            const float2 lo = a2[SLOT[2*j]], hi = a2[SLOT[2*j+1]];
            dst[j] = make_float4(lo.x, lo.y, hi.x, hi.y);
        }
    }
    __syncthreads();

    // ---------- FFT2 pass 1 (m=16, table E): upper -> lower ----------
    if (act) {
        float2 a[16];
        float2* const pu2 = sb + UPO + PAD(tid);
        #pragma unroll
        for (int q = 0; q < 16; q++) a[q] = pu2[272 * q];
        bfly16(a);
        apply_tw15(a, &twid[TBL_E + (tid & ~15)]);   // row = (tid>>4)*16
        float2* const ps = sb + PAD(((tid & ~15) << 4) + (tid & 15));
        #pragma unroll
        for (int q = 0; q < 16; q++)
            ps[16*q + 2*(q >> 1)] = a[SLOT[q]];
    }
    __syncthreads();

    // ---------- FFT2 pass 2 (m=256): twiddle-free, argmax from registers ----------
    // F[n] at n = tid + 256q; corr[2n] = Re, corr[2n+1] = Im.
    float best = -INFINITY;
    int   bidx = 0x7fffffff;
    if (act) {
        float2 a[16];
        float2* const pl2 = sb + PAD(tid);
        #pragma unroll
        for (int q = 0; q < 16; q++) a[q] = pl2[272 * q];
        bfly16(a);
        #pragma unroll
        for (int q = 0; q < 16; q++) {
            const int n = tid + q * 256;             // ascending in q
            const float2 v = a[SLOT[q]];
            if (v.x > best) { best = v.x; bidx = 2 * n; }
            if (v.y > best) { best = v.y; bidx = 2 * n + 1; }
        }
    }

    // ---------- argmax reduction (first-index tiebreak) ----------
    const int lane = tid & 31, wid = tid >> 5;
    #pragma unroll
    for (int off = 16; off > 0; off >>= 1) {
        const float v2 = __shfl_down_sync(0xffffffffu, best, off);
        const int   i2 = __shfl_down_sync(0xffffffffu, bidx, off);
        if (v2 > best || (v2 == best && i2 < bidx)) { best = v2; bidx = i2; }
    }
    if (lane == 0) { wv[wid] = best; wi[wid] = bidx; }
    __syncthreads();
    if (wid == 0) {
        float b2 = (lane < 16) ? wv[lane] : -INFINITY;
        int   j2 = (lane < 16) ? wi[lane] : 0x7fffffff;
        #pragma unroll
        for (int off = 8; off > 0; off >>= 1) {
            const float v2 = __shfl_down_sync(0xffffffffu, b2, off);
            const int   i2 = __shfl_down_sync(0xffffffffu, j2, off);
            if (v2 > b2 || (v2 == b2 && i2 < j2)) { b2 = v2; j2 = i2; }
        }
        if (lane == 0) *fnd = j2;
    }
    __syncthreads();
    const int ind = *fnd;

    // ---------- circular roll (float4 stores, strength-reduced gather) ----------
    float4* out4 = (float4*)(out_aligned + (size_t)row * FFT_N);
    const int k0 = (4 * tid - ind) & (FFT_N - 1);
    #pragma unroll
    for (int i = 0; i < 4; i++) {
        const int b = (k0 + 2048 * i) & (FFT_N - 1);
        float4 v;
        v.x = xr[b];
        v.y = xr[(b + 1) & (FFT_N - 1)];
        v.z = xr[(b + 2) & (FFT_N - 1)];
        v.w = xr[(b + 3) & (FFT_N - 1)];
        out4[tid + i * 512] = v;
    }
    if (tid == 0)
        out_inds[row] = (float)ind;
}

extern "C" void kernel_launch(void* const* d_in, const int* in_sizes, int n_in,
                              void* d_out, int out_size) {
    const float* x    = (const float*)d_in[0];
    const float* xref = (const float*)d_in[1];
    float* out = (float*)d_out;

    const int rows = in_sizes[0] / FFT_N;    // 2048
    float* out_aligned = out;
    float* out_inds    = out + (size_t)rows * FFT_N;

    const size_t smem = PADN * sizeof(float2)
                      + TBL_TOT * sizeof(float2)
                      + 16 * sizeof(float) + 17 * sizeof(int);
    cudaFuncSetAttribute(batch_align_kernel,
                         cudaFuncAttributeMaxDynamicSharedMemorySize, (int)smem);
    batch_align_kernel<<<rows, THREADS, smem>>>(x, xref, out_aligned, out_inds);
}